// round 8
// baseline (speedup 1.0000x reference)
#include <cuda_runtime.h>
#include <math.h>
#include <stdint.h>

#define NNODES 50000
#define TT 8
#define HH 128
#define COUT 32
#define EDGES 800000
#define MROWS 400000

// ======================= scratch (device globals) ============================
__device__ int   g_is64;
__device__ int   g_src[EDGES];
__device__ int   g_dst[EDGES];
__device__ int   g_cnt[NNODES];
__device__ int   g_off[NNODES];
__device__ int   g_cur[NNODES];
__device__ int   g_adj[EDGES];
__device__ float g_AX [(size_t)MROWS*64];      // [m=(n*8+t), 64] = [agg/deg | x]
__device__ float g_Wcat[HH*64];                // [128, 64] = [Wl | Wr]
__device__ float g_Wh [96*HH];                 // [96, 128] = [W_rec ; W_c1]
__device__ float g_bh [96];
__device__ float g_SP [(size_t)MROWS*HH];      // [m, 128]
__device__ float g_GX [(size_t)MROWS*3*HH];    // [m, 384]
__device__ float g_H  [(size_t)NNODES*HH];     // [n, 128]
__device__ float g_HS [(size_t)MROWS*HH];      // [m, 128]

// ======================= helpers =============================================
__device__ __forceinline__ float tf32_rna(float v) {
    uint32_t r;
    asm("cvt.rna.tf32.f32 %0, %1;" : "=r"(r) : "f"(v));
    return __uint_as_float(r);
}
#define MMA_TF32(C, Af, Bf) \
    asm volatile( \
        "mma.sync.aligned.m16n8k8.row.col.f32.tf32.tf32.f32 " \
        "{%0,%1,%2,%3}, {%4,%5,%6,%7}, {%8,%9}, {%0,%1,%2,%3};" \
        : "+f"((C)[0]), "+f"((C)[1]), "+f"((C)[2]), "+f"((C)[3]) \
        : "r"((Af)[0]), "r"((Af)[1]), "r"((Af)[2]), "r"((Af)[3]), \
          "r"((Bf)[0]), "r"((Bf)[1]))
#define CP_ASYNC16(dst, src, sz) \
    asm volatile("cp.async.ca.shared.global [%0], [%1], 16, %2;" \
                 :: "r"(dst), "l"(src), "r"(sz))
__device__ __forceinline__ float sigmoidf_(float v) { return 1.f / (1.f + expf(-v)); }

// ======================= edge dtype detect + convert =========================
__global__ void detect_kernel(const void* ei) {
    const unsigned long long* p = (const unsigned long long*)ei;
    int is64 = 1;
    for (int i = 0; i < 1024; i++)
        if ((p[i] >> 32) != 0ull) { is64 = 0; break; }
    g_is64 = is64;
}
__global__ void convert_kernel(const void* ei) {
    int e = blockIdx.x * blockDim.x + threadIdx.x;
    if (e >= EDGES) return;
    int s, d;
    if (g_is64) {
        const long long* p = (const long long*)ei;
        s = (int)p[e]; d = (int)p[EDGES + e];
    } else {
        const int* p = (const int*)ei;
        s = p[e]; d = p[EDGES + e];
    }
    s = min(max(s, 0), NNODES - 1);
    d = min(max(d, 0), NNODES - 1);
    g_src[e] = s;
    g_dst[e] = d;
}

// ======================= graph prep ==========================================
__global__ void zero_kernel() {
    int idx = blockIdx.x * blockDim.x + threadIdx.x;
    int stride = gridDim.x * blockDim.x;
    for (size_t i = idx; i < (size_t)NNODES*HH; i += stride) g_H[i] = 0.f;
    for (int i = idx; i < NNODES; i += stride) g_cnt[i] = 0;
}
__global__ void count_kernel() {
    int e = blockIdx.x * blockDim.x + threadIdx.x;
    if (e < EDGES) atomicAdd(&g_cnt[g_dst[e]], 1);
}
__global__ void scan_kernel() {
    __shared__ int partial[1024];
    const int CH = (NNODES + 1023) / 1024;
    int t = threadIdx.x;
    int begin = t * CH;
    int end   = min(begin + CH, NNODES);
    int s = 0;
    for (int i = begin; i < end; i++) s += g_cnt[i];
    partial[t] = s;
    __syncthreads();
    #pragma unroll
    for (int d = 1; d < 1024; d <<= 1) {
        int v = (t >= d) ? partial[t - d] : 0;
        __syncthreads();
        partial[t] += v;
        __syncthreads();
    }
    int off = partial[t] - s;
    for (int i = begin; i < end; i++) {
        g_off[i] = off;
        g_cur[i] = off;
        off += g_cnt[i];
    }
}
__global__ void fill_kernel() {
    int e = blockIdx.x * blockDim.x + threadIdx.x;
    if (e >= EDGES) return;
    int pos = atomicAdd(&g_cur[g_dst[e]], 1);
    g_adj[pos] = g_src[e];
}
__global__ void __launch_bounds__(256) gather_kernel(const float* __restrict__ x) {
    int n   = blockIdx.x;
    int idx = threadIdx.x;
    int beg = g_off[n];
    int cnt = g_cnt[n];
    float s = 0.f;
    for (int p = beg; p < beg + cnt; p++) {
        int src = g_adj[p];
        s += x[(size_t)src * 256 + idx];
    }
    float dg = fmaxf((float)cnt, 1.f);
    int t = idx >> 5, c = idx & 31;
    size_t m = (size_t)n * 8 + t;
    g_AX[m * 64 + c]      = s / dg;
    g_AX[m * 64 + 32 + c] = x[(size_t)n * 256 + idx];
}
__global__ void wcat_kernel(const float* __restrict__ Wl, const float* __restrict__ Wr) {
    int idx = blockIdx.x * blockDim.x + threadIdx.x;
    if (idx >= HH*64) return;
    int j = idx >> 6, c = idx & 63;
    g_Wcat[idx] = (c < 32) ? Wl[j*32 + c] : Wr[j*32 + (c-32)];
}
__global__ void headcat_kernel(const float* __restrict__ W_rec, const float* __restrict__ b_rec,
                               const float* __restrict__ W_c1,  const float* __restrict__ b_c1) {
    int idx = blockIdx.x * blockDim.x + threadIdx.x;
    if (idx < 96*HH) {
        int r = idx >> 7, k = idx & 127;
        g_Wh[idx] = (r < 32) ? W_rec[r*128 + k] : W_c1[(r-32)*128 + k];
    }
    if (idx < 96) g_bh[idx] = (idx < 32) ? b_rec[idx] : b_c1[idx - 32];
}

// ======================= mma.sync 3xTF32 GEMM (SP / GX / head) ===============
// block tile 128x128, 512 thr (16 warps 4x4), warp tile 32x32. 2-stage cp.async.
// ACT: 0 linear, 1 relu, 2 head (col<32 linear->C ld32; 32..95 relu->smem->cls)
#define SROW 36
#define SMAT (128*SROW)
#define GSMEM (2*2*SMAT*4)             /* 73728 B */
#define C1S   72                       /* smem stride for head c1 stage */

template<int KC, int ACT>
__global__ void __launch_bounds__(512, 1) mma_gemm(
    int M, int nW,
    const float* __restrict__ A, int lda,
    const float* __restrict__ W, int ldw,
    const float* __restrict__ bias,
    float* __restrict__ C, int ldc,
    const float* __restrict__ w2, const float* __restrict__ b2,
    float* __restrict__ clsOut)
{
    extern __shared__ float smem[];
    uint32_t smem_b;
    asm("{ .reg .u64 t; cvta.to.shared.u64 t, %1; cvt.u32.u64 %0, t; }"
        : "=r"(smem_b) : "l"(smem));

    const int tid  = threadIdx.x;
    const int lane = tid & 31;
    const int w    = tid >> 5;
    const int gid  = lane >> 2;
    const int tig  = lane & 3;
    const int wm   = w >> 2;
    const int wn   = w & 3;
    const int bm   = blockIdx.x * 128;
    const int bn   = blockIdx.y * 128;

    float acc[2][4][4];
    #pragma unroll
    for (int i = 0; i < 2; i++)
        #pragma unroll
        for (int j = 0; j < 4; j++)
            #pragma unroll
            for (int k = 0; k < 4; k++) acc[i][j][k] = 0.f;

    auto issue_copy = [&](int kc) {
        const int s = kc & 1;
        const uint32_t abase = smem_b + (uint32_t)(s * 2 * SMAT) * 4u;
        const uint32_t bbase = abase + (uint32_t)SMAT * 4u;
        #pragma unroll
        for (int h = 0; h < 2; h++) {
            int i   = tid + h * 512;
            int row = i >> 3;
            int seg = i & 7;
            uint32_t soff = (uint32_t)(row * SROW + seg * 4) * 4u;
            {
                int grow = bm + row;
                const float* src = A + (size_t)min(grow, M - 1) * lda + kc * 32 + seg * 4;
                CP_ASYNC16(abase + soff, src, (grow < M) ? 16 : 0);
            }
            {
                int grow = bn + row;
                const float* src = W + (size_t)min(grow, nW - 1) * ldw + kc * 32 + seg * 4;
                CP_ASYNC16(bbase + soff, src, (grow < nW) ? 16 : 0);
            }
        }
        asm volatile("cp.async.commit_group;" ::: "memory");
    };

    issue_copy(0);

    for (int kc = 0; kc < KC; kc++) {
        if (kc + 1 < KC) {
            issue_copy(kc + 1);
            asm volatile("cp.async.wait_group 1;" ::: "memory");
        } else {
            asm volatile("cp.async.wait_group 0;" ::: "memory");
        }
        __syncthreads();

        const float* Af = smem + (kc & 1) * 2 * SMAT;
        const float* Bf = Af + SMAT;

        #pragma unroll
        for (int k8 = 0; k8 < 4; k8++) {
            const int k0 = k8 * 8;
            float ar[2][4], br[4][2];
            #pragma unroll
            for (int mt = 0; mt < 2; mt++) {
                int r0 = wm*32 + mt*16 + gid;
                ar[mt][0] = Af[ r0      *SROW + k0 + tig    ];
                ar[mt][1] = Af[(r0 + 8) *SROW + k0 + tig    ];
                ar[mt][2] = Af[ r0      *SROW + k0 + tig + 4];
                ar[mt][3] = Af[(r0 + 8) *SROW + k0 + tig + 4];
            }
            #pragma unroll
            for (int nt = 0; nt < 4; nt++) {
                int cb = wn*32 + nt*8 + gid;
                br[nt][0] = Bf[cb*SROW + k0 + tig    ];
                br[nt][1] = Bf[cb*SROW + k0 + tig + 4];
            }
            uint32_t afh[2][4], afl[2][4], bfh[4][2], bfl[4][2];
            #pragma unroll
            for (int mt = 0; mt < 2; mt++)
                #pragma unroll
                for (int q = 0; q < 4; q++) {
                    float hi = tf32_rna(ar[mt][q]);
                    afh[mt][q] = __float_as_uint(hi);
                    afl[mt][q] = __float_as_uint(ar[mt][q] - hi);
                }
            #pragma unroll
            for (int nt = 0; nt < 4; nt++)
                #pragma unroll
                for (int q = 0; q < 2; q++) {
                    float hi = tf32_rna(br[nt][q]);
                    bfh[nt][q] = __float_as_uint(hi);
                    bfl[nt][q] = __float_as_uint(br[nt][q] - hi);
                }
            #pragma unroll
            for (int mt = 0; mt < 2; mt++)
                #pragma unroll
                for (int nt = 0; nt < 4; nt++) {
                    MMA_TF32(acc[mt][nt], afh[mt], bfh[nt]);
                    MMA_TF32(acc[mt][nt], afh[mt], bfl[nt]);
                    MMA_TF32(acc[mt][nt], afl[mt], bfh[nt]);
                }
        }
        __syncthreads();
    }

    // ---- epilogue ----
    #pragma unroll
    for (int mt = 0; mt < 2; mt++) {
        #pragma unroll
        for (int nt = 0; nt < 4; nt++) {
            int col = bn + wn*32 + nt*8 + 2*tig;
            #pragma unroll
            for (int half = 0; half < 2; half++) {
                int row = bm + wm*32 + mt*16 + gid + half*8;
                if (row >= M) continue;
                float2 o;
                o.x = acc[mt][nt][half*2 + 0];
                o.y = acc[mt][nt][half*2 + 1];
                if (ACT == 2) {
                    if (col >= 96) continue;
                    o.x += bias[col];
                    o.y += bias[col + 1];
                    if (col < 32) {
                        *(float2*)(C + (size_t)row*32 + col) = o;
                    } else {
                        o.x = fmaxf(o.x, 0.f);
                        o.y = fmaxf(o.y, 0.f);
                        int lrow = row - bm;
                        smem[lrow*C1S + col - 32]     = o.x;
                        smem[lrow*C1S + col - 32 + 1] = o.y;
                    }
                } else {
                    o.x += bias[col];
                    o.y += bias[col + 1];
                    if (ACT == 1) {
                        o.x = fmaxf(o.x, 0.f);
                        o.y = fmaxf(o.y, 0.f);
                    }
                    *(float2*)(C + (size_t)row*ldc + col) = o;
                }
            }
        }
    }

    if (ACT == 2) {
        __syncthreads();
        // 16 warps x 8 rows: cls[row] = sigmoid(dot(c1[row,:64], w2) + b2)
        #pragma unroll
        for (int rr = 0; rr < 8; rr++) {
            int lrow = w*8 + rr;
            float s = smem[lrow*C1S + lane]      * w2[lane]
                    + smem[lrow*C1S + 32 + lane] * w2[32 + lane];
            #pragma unroll
            for (int o = 16; o; o >>= 1) s += __shfl_xor_sync(0xffffffffu, s, o);
            if (lane == 0) clsOut[bm + lrow] = sigmoidf_(s + b2[0]);
        }
    }
}

// ======================= fused GH GEMM + GRU =================================
// Per timestep t: gh = H @ W_hh^T + b_hh (block 64 rows x ALL 384 cols), then
// GRU update in-epilogue: H/HS updated in place. 256 thr = 8 warps (2m x 4n),
// warp tile 32x96 (2x12 frags). 2-stage cp.async pipe, gh staged in smem.
#define GH_ASZ  (64*SROW)              /* 2304 words */
#define GH_BSZ  (384*SROW)             /* 13824 words */
#define GH_STG  (GH_ASZ + GH_BSZ)      /* 16128 words */
#define GH_SMEM (2*GH_STG*4)           /* 129024 B */
#define GHS     390                    /* epilogue gh stage stride (words) */

__global__ void __launch_bounds__(256, 1) ghgru_kernel(
    int t,
    const float* __restrict__ W_hh,
    const float* __restrict__ b_hh)
{
    extern __shared__ float smem[];
    uint32_t smem_b;
    asm("{ .reg .u64 t; cvta.to.shared.u64 t, %1; cvt.u32.u64 %0, t; }"
        : "=r"(smem_b) : "l"(smem));

    const int tid  = threadIdx.x;
    const int lane = tid & 31;
    const int w    = tid >> 5;
    const int gid  = lane >> 2;
    const int tig  = lane & 3;
    const int wm   = w >> 2;        // 0..1
    const int wn   = w & 3;         // 0..3
    const int bm   = blockIdx.x * 64;

    float acc[2][12][4];
    #pragma unroll
    for (int i = 0; i < 2; i++)
        #pragma unroll
        for (int j = 0; j < 12; j++)
            #pragma unroll
            for (int k = 0; k < 4; k++) acc[i][j][k] = 0.f;

    auto issue_copy = [&](int kc) {
        const int s = kc & 1;
        const uint32_t abase = smem_b + (uint32_t)(s * GH_STG) * 4u;
        const uint32_t bbase = abase + (uint32_t)GH_ASZ * 4u;
        // A: 64 rows x 8 segs = 512 -> 2/thread
        #pragma unroll
        for (int h = 0; h < 2; h++) {
            int i   = tid + h * 256;
            int row = i >> 3;
            int seg = i & 7;
            uint32_t soff = (uint32_t)(row * SROW + seg * 4) * 4u;
            int grow = bm + row;
            const float* src = g_H + (size_t)min(grow, NNODES - 1) * HH + kc * 32 + seg * 4;
            CP_ASYNC16(abase + soff, src, (grow < NNODES) ? 16 : 0);
        }
        // B: 384 rows x 8 segs = 3072 -> 12/thread
        #pragma unroll
        for (int h = 0; h < 12; h++) {
            int i   = tid + h * 256;
            int row = i >> 3;
            int seg = i & 7;
            uint32_t soff = (uint32_t)(row * SROW + seg * 4) * 4u;
            const float* src = W_hh + (size_t)row * HH + kc * 32 + seg * 4;
            CP_ASYNC16(bbase + soff, src, 16);
        }
        asm volatile("cp.async.commit_group;" ::: "memory");
    };

    issue_copy(0);

    for (int kc = 0; kc < 4; kc++) {
        if (kc + 1 < 4) {
            issue_copy(kc + 1);
            asm volatile("cp.async.wait_group 1;" ::: "memory");
        } else {
            asm volatile("cp.async.wait_group 0;" ::: "memory");
        }
        __syncthreads();

        const float* Af = smem + (kc & 1) * GH_STG;
        const float* Bf = Af + GH_ASZ;

        #pragma unroll
        for (int k8 = 0; k8 < 4; k8++) {
            const int k0 = k8 * 8;
            float ar[2][4];
            uint32_t afh[2][4], afl[2][4];
            #pragma unroll
            for (int mt = 0; mt < 2; mt++) {
                int r0 = wm*32 + mt*16 + gid;
                ar[mt][0] = Af[ r0      *SROW + k0 + tig    ];
                ar[mt][1] = Af[(r0 + 8) *SROW + k0 + tig    ];
                ar[mt][2] = Af[ r0      *SROW + k0 + tig + 4];
                ar[mt][3] = Af[(r0 + 8) *SROW + k0 + tig + 4];
                #pragma unroll
                for (int q = 0; q < 4; q++) {
                    float hi = tf32_rna(ar[mt][q]);
                    afh[mt][q] = __float_as_uint(hi);
                    afl[mt][q] = __float_as_uint(ar[mt][q] - hi);
                }
            }
            #pragma unroll
            for (int nt = 0; nt < 12; nt++) {
                int cb = wn*96 + nt*8 + gid;
                float b0 = Bf[cb*SROW + k0 + tig    ];
                float b1 = Bf[cb*SROW + k0 + tig + 4];
                uint32_t bfh[2], bfl[2];
                float h0 = tf32_rna(b0), h1 = tf32_rna(b1);
                bfh[0] = __float_as_uint(h0); bfl[0] = __float_as_uint(b0 - h0);
                bfh[1] = __float_as_uint(h1); bfl[1] = __float_as_uint(b1 - h1);
                #pragma unroll
                for (int mt = 0; mt < 2; mt++) {
                    MMA_TF32(acc[mt][nt], afh[mt], bfh);
                    MMA_TF32(acc[mt][nt], afh[mt], bfl);
                    MMA_TF32(acc[mt][nt], afl[mt], bfh);
                }
            }
        }
        __syncthreads();
    }

    // ---- stage gh(+bias) into smem [64][384] ----
    #pragma unroll
    for (int mt = 0; mt < 2; mt++) {
        #pragma unroll
        for (int nt = 0; nt < 12; nt++) {
            int col = wn*96 + nt*8 + 2*tig;
            #pragma unroll
            for (int half = 0; half < 2; half++) {
                int lrow = wm*32 + mt*16 + gid + half*8;
                smem[lrow*GHS + col]     = acc[mt][nt][half*2 + 0] + b_hh[col];
                smem[lrow*GHS + col + 1] = acc[mt][nt][half*2 + 1] + b_hh[col + 1];
            }
        }
    }
    __syncthreads();

    // ---- GRU pointwise: 64 rows x 128 -> 32 elements/thread ----
    for (int e = tid; e < 64*128; e += 256) {
        int lrow = e >> 7;
        int j    = e & 127;
        int i    = bm + lrow;
        if (i >= NNODES) continue;
        size_t m = (size_t)i*8 + t;
        float gxr = g_GX[m*384 + j];
        float gxz = g_GX[m*384 + 128 + j];
        float gxn = g_GX[m*384 + 256 + j];
        float ghr = smem[lrow*GHS + j];
        float ghz = smem[lrow*GHS + 128 + j];
        float ghn = smem[lrow*GHS + 256 + j];
        float r  = sigmoidf_(gxr + ghr);
        float z  = sigmoidf_(gxz + ghz);
        float nn = tanhf(gxn + r*ghn);
        float h  = g_H[(size_t)i*HH + j];
        float hn = (1.f - z)*nn + z*h;
        g_H[(size_t)i*HH + j] = hn;
        g_HS[m*HH + j] = hn;
    }
}

// ======================= launch ==============================================
extern "C" void kernel_launch(void* const* d_in, const int* in_sizes, int n_in,
                              void* d_out, int out_size)
{
    const float* x     = (const float*)d_in[0];
    const void*  ei    = d_in[1];
    const float* Wl    = (const float*)d_in[2];
    const float* bl    = (const float*)d_in[3];
    const float* Wr    = (const float*)d_in[4];
    const float* W_ih  = (const float*)d_in[5];
    const float* b_ih  = (const float*)d_in[6];
    const float* W_hh  = (const float*)d_in[7];
    const float* b_hh  = (const float*)d_in[8];
    const float* W_rec = (const float*)d_in[9];
    const float* b_rec = (const float*)d_in[10];
    const float* W_c1  = (const float*)d_in[11];
    const float* b_c1  = (const float*)d_in[12];
    const float* W_c2  = (const float*)d_in[13];
    const float* b_c2  = (const float*)d_in[14];

    float* out      = (float*)d_out;
    float* outRecon = out;                          // [N,T,32] flat, row m
    float* outCls   = out + (size_t)MROWS * COUT;   // [N,T] flat, row m

    float *pAX, *pWcat, *pSP, *pGX, *pHS, *pWh, *pbh;
    cudaGetSymbolAddress((void**)&pAX,   g_AX);
    cudaGetSymbolAddress((void**)&pWcat, g_Wcat);
    cudaGetSymbolAddress((void**)&pSP,   g_SP);
    cudaGetSymbolAddress((void**)&pGX,   g_GX);
    cudaGetSymbolAddress((void**)&pHS,   g_HS);
    cudaGetSymbolAddress((void**)&pWh,   g_Wh);
    cudaGetSymbolAddress((void**)&pbh,   g_bh);

    cudaFuncSetAttribute(mma_gemm<2,1>, cudaFuncAttributeMaxDynamicSharedMemorySize, GSMEM);
    cudaFuncSetAttribute(mma_gemm<4,0>, cudaFuncAttributeMaxDynamicSharedMemorySize, GSMEM);
    cudaFuncSetAttribute(mma_gemm<4,2>, cudaFuncAttributeMaxDynamicSharedMemorySize, GSMEM);
    cudaFuncSetAttribute(ghgru_kernel,  cudaFuncAttributeMaxDynamicSharedMemorySize, GH_SMEM);

    // graph prep
    detect_kernel<<<1, 1>>>(ei);
    convert_kernel<<<(EDGES + 255)/256, 256>>>(ei);
    zero_kernel<<<1024, 256>>>();
    wcat_kernel<<<(HH*64 + 255)/256, 256>>>(Wl, Wr);
    headcat_kernel<<<(96*HH + 255)/256, 256>>>(W_rec, b_rec, W_c1, b_c1);
    count_kernel<<<(EDGES + 255)/256, 256>>>();
    scan_kernel<<<1, 1024>>>();
    fill_kernel<<<(EDGES + 255)/256, 256>>>();
    gather_kernel<<<NNODES, 256>>>(x);

    // SP = relu(AX @ Wcat^T + bl): [400000,64] -> [400000,128]
    mma_gemm<2,1><<<dim3(MROWS/128, 1), 512, GSMEM>>>(
        MROWS, 128, pAX, 64, pWcat, 64, bl, pSP, 128, nullptr, nullptr, nullptr);

    // GX = SP @ W_ih^T + b_ih: [400000,128] -> [400000,384]
    mma_gemm<4,0><<<dim3(MROWS/128, 3), 512, GSMEM>>>(
        MROWS, 384, pSP, 128, W_ih, 128, b_ih, pGX, 384, nullptr, nullptr, nullptr);

    // recurrence: fused GH GEMM + GRU, 8 launches
    for (int t = 0; t < TT; t++)
        ghgru_kernel<<<(NNODES + 63)/64, 256, GH_SMEM>>>(t, W_hh, b_hh);

    // heads: recon (linear, ld32 -> d_out) + c1(relu, smem) + cls (fused)
    mma_gemm<4,2><<<dim3(MROWS/128, 1), 512, GSMEM>>>(
        MROWS, 96, pHS, 128, pWh, 128, pbh, outRecon, 32, W_c2, b_c2, outCls);
}

// round 9
// speedup vs baseline: 1.3457x; 1.3457x over previous
#include <cuda_runtime.h>
#include <math.h>
#include <stdint.h>

#define NNODES 50000
#define TT 8
#define HH 128
#define COUT 32
#define EDGES 800000
#define MROWS 400000

// ======================= scratch (device globals) ============================
__device__ int   g_is64;
__device__ int   g_src[EDGES];
__device__ int   g_dst[EDGES];
__device__ int   g_cnt[NNODES];
__device__ int   g_off[NNODES];
__device__ int   g_cur[NNODES];
__device__ int   g_adj[EDGES];
__device__ float g_AX [(size_t)MROWS*64];      // [m=(n*8+t), 64] = [agg/deg | x]
__device__ float g_Wcat[HH*64];                // [128, 64] = [Wl | Wr]
__device__ float g_Wh [96*HH];                 // [96, 128] = [W_rec ; W_c1]
__device__ float g_bh [96];
__device__ float g_SP [(size_t)MROWS*HH];      // [m, 128]
__device__ float g_GX [(size_t)MROWS*3*HH];    // [m, 384]
__device__ float g_H  [(size_t)NNODES*HH];     // [n, 128]
__device__ float g_HS [(size_t)MROWS*HH];      // [m, 128]

// ======================= helpers =============================================
__device__ __forceinline__ float tf32_rna(float v) {
    uint32_t r;
    asm("cvt.rna.tf32.f32 %0, %1;" : "=r"(r) : "f"(v));
    return __uint_as_float(r);
}
#define MMA_TF32(C, Af, Bf) \
    asm volatile( \
        "mma.sync.aligned.m16n8k8.row.col.f32.tf32.tf32.f32 " \
        "{%0,%1,%2,%3}, {%4,%5,%6,%7}, {%8,%9}, {%0,%1,%2,%3};" \
        : "+f"((C)[0]), "+f"((C)[1]), "+f"((C)[2]), "+f"((C)[3]) \
        : "r"((Af)[0]), "r"((Af)[1]), "r"((Af)[2]), "r"((Af)[3]), \
          "r"((Bf)[0]), "r"((Bf)[1]))
#define CP_ASYNC16(dst, src, sz) \
    asm volatile("cp.async.ca.shared.global [%0], [%1], 16, %2;" \
                 :: "r"(dst), "l"(src), "r"(sz))
__device__ __forceinline__ float sigmoidf_(float v) { return 1.f / (1.f + expf(-v)); }

// ======================= edge dtype detect + convert =========================
__global__ void detect_kernel(const void* ei) {
    const unsigned long long* p = (const unsigned long long*)ei;
    int is64 = 1;
    for (int i = 0; i < 1024; i++)
        if ((p[i] >> 32) != 0ull) { is64 = 0; break; }
    g_is64 = is64;
}
__global__ void convert_kernel(const void* ei) {
    int e = blockIdx.x * blockDim.x + threadIdx.x;
    if (e >= EDGES) return;
    int s, d;
    if (g_is64) {
        const long long* p = (const long long*)ei;
        s = (int)p[e]; d = (int)p[EDGES + e];
    } else {
        const int* p = (const int*)ei;
        s = p[e]; d = p[EDGES + e];
    }
    s = min(max(s, 0), NNODES - 1);
    d = min(max(d, 0), NNODES - 1);
    g_src[e] = s;
    g_dst[e] = d;
}

// ======================= graph prep ==========================================
__global__ void zero_kernel() {
    int idx = blockIdx.x * blockDim.x + threadIdx.x;
    int stride = gridDim.x * blockDim.x;
    for (size_t i = idx; i < (size_t)NNODES*HH; i += stride) g_H[i] = 0.f;
    for (int i = idx; i < NNODES; i += stride) g_cnt[i] = 0;
}
__global__ void count_kernel() {
    int e = blockIdx.x * blockDim.x + threadIdx.x;
    if (e < EDGES) atomicAdd(&g_cnt[g_dst[e]], 1);
}
__global__ void scan_kernel() {
    __shared__ int partial[1024];
    const int CH = (NNODES + 1023) / 1024;
    int t = threadIdx.x;
    int begin = t * CH;
    int end   = min(begin + CH, NNODES);
    int s = 0;
    for (int i = begin; i < end; i++) s += g_cnt[i];
    partial[t] = s;
    __syncthreads();
    #pragma unroll
    for (int d = 1; d < 1024; d <<= 1) {
        int v = (t >= d) ? partial[t - d] : 0;
        __syncthreads();
        partial[t] += v;
        __syncthreads();
    }
    int off = partial[t] - s;
    for (int i = begin; i < end; i++) {
        g_off[i] = off;
        g_cur[i] = off;
        off += g_cnt[i];
    }
}
__global__ void fill_kernel() {
    int e = blockIdx.x * blockDim.x + threadIdx.x;
    if (e >= EDGES) return;
    int pos = atomicAdd(&g_cur[g_dst[e]], 1);
    g_adj[pos] = g_src[e];
}
__global__ void __launch_bounds__(256) gather_kernel(const float* __restrict__ x) {
    int n   = blockIdx.x;
    int idx = threadIdx.x;
    int beg = g_off[n];
    int cnt = g_cnt[n];
    float s = 0.f;
    for (int p = beg; p < beg + cnt; p++) {
        int src = g_adj[p];
        s += x[(size_t)src * 256 + idx];
    }
    float dg = fmaxf((float)cnt, 1.f);
    int t = idx >> 5, c = idx & 31;
    size_t m = (size_t)n * 8 + t;
    g_AX[m * 64 + c]      = s / dg;
    g_AX[m * 64 + 32 + c] = x[(size_t)n * 256 + idx];
}
__global__ void wcat_kernel(const float* __restrict__ Wl, const float* __restrict__ Wr) {
    int idx = blockIdx.x * blockDim.x + threadIdx.x;
    if (idx >= HH*64) return;
    int j = idx >> 6, c = idx & 63;
    g_Wcat[idx] = (c < 32) ? Wl[j*32 + c] : Wr[j*32 + (c-32)];
}
__global__ void headcat_kernel(const float* __restrict__ W_rec, const float* __restrict__ b_rec,
                               const float* __restrict__ W_c1,  const float* __restrict__ b_c1) {
    int idx = blockIdx.x * blockDim.x + threadIdx.x;
    if (idx < 96*HH) {
        int r = idx >> 7, k = idx & 127;
        g_Wh[idx] = (r < 32) ? W_rec[r*128 + k] : W_c1[(r-32)*128 + k];
    }
    if (idx < 96) g_bh[idx] = (idx < 32) ? b_rec[idx] : b_c1[idx - 32];
}

// ======================= mma.sync 3xTF32 GEMM (SP / GX / head) ===============
// block tile 128x128, 512 thr (16 warps 4x4), warp tile 32x32. 2-stage cp.async.
// ACT: 0 linear, 1 relu, 2 head (col<32 linear->C ld32; 32..95 relu->smem->cls)
#define SROW 36
#define SMAT (128*SROW)
#define GSMEM (2*2*SMAT*4)             /* 73728 B */
#define C1S   72                       /* smem stride for head c1 stage */

template<int KC, int ACT>
__global__ void __launch_bounds__(512, 1) mma_gemm(
    int M, int nW,
    const float* __restrict__ A, int lda,
    const float* __restrict__ W, int ldw,
    const float* __restrict__ bias,
    float* __restrict__ C, int ldc,
    const float* __restrict__ w2, const float* __restrict__ b2,
    float* __restrict__ clsOut)
{
    extern __shared__ float smem[];
    uint32_t smem_b;
    asm("{ .reg .u64 t; cvta.to.shared.u64 t, %1; cvt.u32.u64 %0, t; }"
        : "=r"(smem_b) : "l"(smem));

    const int tid  = threadIdx.x;
    const int lane = tid & 31;
    const int w    = tid >> 5;
    const int gid  = lane >> 2;
    const int tig  = lane & 3;
    const int wm   = w >> 2;
    const int wn   = w & 3;
    const int bm   = blockIdx.x * 128;
    const int bn   = blockIdx.y * 128;

    float acc[2][4][4];
    #pragma unroll
    for (int i = 0; i < 2; i++)
        #pragma unroll
        for (int j = 0; j < 4; j++)
            #pragma unroll
            for (int k = 0; k < 4; k++) acc[i][j][k] = 0.f;

    auto issue_copy = [&](int kc) {
        const int s = kc & 1;
        const uint32_t abase = smem_b + (uint32_t)(s * 2 * SMAT) * 4u;
        const uint32_t bbase = abase + (uint32_t)SMAT * 4u;
        #pragma unroll
        for (int h = 0; h < 2; h++) {
            int i   = tid + h * 512;
            int row = i >> 3;
            int seg = i & 7;
            uint32_t soff = (uint32_t)(row * SROW + seg * 4) * 4u;
            {
                int grow = bm + row;
                const float* src = A + (size_t)min(grow, M - 1) * lda + kc * 32 + seg * 4;
                CP_ASYNC16(abase + soff, src, (grow < M) ? 16 : 0);
            }
            {
                int grow = bn + row;
                const float* src = W + (size_t)min(grow, nW - 1) * ldw + kc * 32 + seg * 4;
                CP_ASYNC16(bbase + soff, src, (grow < nW) ? 16 : 0);
            }
        }
        asm volatile("cp.async.commit_group;" ::: "memory");
    };

    issue_copy(0);

    for (int kc = 0; kc < KC; kc++) {
        if (kc + 1 < KC) {
            issue_copy(kc + 1);
            asm volatile("cp.async.wait_group 1;" ::: "memory");
        } else {
            asm volatile("cp.async.wait_group 0;" ::: "memory");
        }
        __syncthreads();

        const float* Af = smem + (kc & 1) * 2 * SMAT;
        const float* Bf = Af + SMAT;

        #pragma unroll
        for (int k8 = 0; k8 < 4; k8++) {
            const int k0 = k8 * 8;
            float ar[2][4], br[4][2];
            #pragma unroll
            for (int mt = 0; mt < 2; mt++) {
                int r0 = wm*32 + mt*16 + gid;
                ar[mt][0] = Af[ r0      *SROW + k0 + tig    ];
                ar[mt][1] = Af[(r0 + 8) *SROW + k0 + tig    ];
                ar[mt][2] = Af[ r0      *SROW + k0 + tig + 4];
                ar[mt][3] = Af[(r0 + 8) *SROW + k0 + tig + 4];
            }
            #pragma unroll
            for (int nt = 0; nt < 4; nt++) {
                int cb = wn*32 + nt*8 + gid;
                br[nt][0] = Bf[cb*SROW + k0 + tig    ];
                br[nt][1] = Bf[cb*SROW + k0 + tig + 4];
            }
            uint32_t afh[2][4], afl[2][4], bfh[4][2], bfl[4][2];
            #pragma unroll
            for (int mt = 0; mt < 2; mt++)
                #pragma unroll
                for (int q = 0; q < 4; q++) {
                    float hi = tf32_rna(ar[mt][q]);
                    afh[mt][q] = __float_as_uint(hi);
                    afl[mt][q] = __float_as_uint(ar[mt][q] - hi);
                }
            #pragma unroll
            for (int nt = 0; nt < 4; nt++)
                #pragma unroll
                for (int q = 0; q < 2; q++) {
                    float hi = tf32_rna(br[nt][q]);
                    bfh[nt][q] = __float_as_uint(hi);
                    bfl[nt][q] = __float_as_uint(br[nt][q] - hi);
                }
            #pragma unroll
            for (int mt = 0; mt < 2; mt++)
                #pragma unroll
                for (int nt = 0; nt < 4; nt++) {
                    MMA_TF32(acc[mt][nt], afh[mt], bfh[nt]);
                    MMA_TF32(acc[mt][nt], afh[mt], bfl[nt]);
                    MMA_TF32(acc[mt][nt], afl[mt], bfh[nt]);
                }
        }
        __syncthreads();
    }

    // ---- epilogue ----
    #pragma unroll
    for (int mt = 0; mt < 2; mt++) {
        #pragma unroll
        for (int nt = 0; nt < 4; nt++) {
            int col = bn + wn*32 + nt*8 + 2*tig;
            #pragma unroll
            for (int half = 0; half < 2; half++) {
                int row = bm + wm*32 + mt*16 + gid + half*8;
                if (row >= M) continue;
                float2 o;
                o.x = acc[mt][nt][half*2 + 0];
                o.y = acc[mt][nt][half*2 + 1];
                if (ACT == 2) {
                    if (col >= 96) continue;
                    o.x += bias[col];
                    o.y += bias[col + 1];
                    if (col < 32) {
                        *(float2*)(C + (size_t)row*32 + col) = o;
                    } else {
                        o.x = fmaxf(o.x, 0.f);
                        o.y = fmaxf(o.y, 0.f);
                        int lrow = row - bm;
                        smem[lrow*C1S + col - 32]     = o.x;
                        smem[lrow*C1S + col - 32 + 1] = o.y;
                    }
                } else {
                    o.x += bias[col];
                    o.y += bias[col + 1];
                    if (ACT == 1) {
                        o.x = fmaxf(o.x, 0.f);
                        o.y = fmaxf(o.y, 0.f);
                    }
                    *(float2*)(C + (size_t)row*ldc + col) = o;
                }
            }
        }
    }

    if (ACT == 2) {
        __syncthreads();
        #pragma unroll
        for (int rr = 0; rr < 8; rr++) {
            int lrow = w*8 + rr;
            float s = smem[lrow*C1S + lane]      * w2[lane]
                    + smem[lrow*C1S + 32 + lane] * w2[32 + lane];
            #pragma unroll
            for (int o = 16; o; o >>= 1) s += __shfl_xor_sync(0xffffffffu, s, o);
            if (lane == 0) clsOut[bm + lrow] = sigmoidf_(s + b2[0]);
        }
    }
}

// ======================= fused GH GEMM + register GRU ========================
// Per timestep t: CTA tile 64 H-rows x ALL 384 gate cols. 512 thr = 16 warps
// (4m x 4n): warp tile 16 rows x (32 cols x 3 gates) -> acc[3][4][4].
// Each thread's fragments hold the r/z/n triplet for its (row,col) positions,
// so the GRU runs entirely in registers in the epilogue. 2-stage cp.async.
#define GH_ASZ  (64*SROW)              /* 2304 words */
#define GH_BSZ  (384*SROW)             /* 13824 words */
#define GH_STG  (GH_ASZ + GH_BSZ)      /* 16128 words */
#define GH_SMEM (2*GH_STG*4)           /* 129024 B */

__global__ void __launch_bounds__(512, 1) ghgru_kernel(
    int t,
    const float* __restrict__ W_hh,
    const float* __restrict__ b_hh)
{
    extern __shared__ float smem[];
    uint32_t smem_b;
    asm("{ .reg .u64 t; cvta.to.shared.u64 t, %1; cvt.u32.u64 %0, t; }"
        : "=r"(smem_b) : "l"(smem));

    const int tid  = threadIdx.x;
    const int lane = tid & 31;
    const int w    = tid >> 5;
    const int gid  = lane >> 2;
    const int tig  = lane & 3;
    const int wm   = w >> 2;        // 0..3 (16 rows each)
    const int wn   = w & 3;         // 0..3 (32 cols each)
    const int bm   = blockIdx.x * 64;

    float acc[3][4][4];
    #pragma unroll
    for (int g = 0; g < 3; g++)
        #pragma unroll
        for (int j = 0; j < 4; j++)
            #pragma unroll
            for (int k = 0; k < 4; k++) acc[g][j][k] = 0.f;

    auto issue_copy = [&](int kc) {
        const int s = kc & 1;
        const uint32_t abase = smem_b + (uint32_t)(s * GH_STG) * 4u;
        const uint32_t bbase = abase + (uint32_t)GH_ASZ * 4u;
        // A: 64 rows x 8 segs = 512 -> 1/thread
        {
            int row = tid >> 3;
            int seg = tid & 7;
            uint32_t soff = (uint32_t)(row * SROW + seg * 4) * 4u;
            int grow = bm + row;
            const float* src = g_H + (size_t)min(grow, NNODES - 1) * HH + kc * 32 + seg * 4;
            CP_ASYNC16(abase + soff, src, (grow < NNODES) ? 16 : 0);
        }
        // B: 384 rows x 8 segs = 3072 -> 6/thread
        #pragma unroll
        for (int h = 0; h < 6; h++) {
            int i   = tid + h * 512;
            int row = i >> 3;
            int seg = i & 7;
            uint32_t soff = (uint32_t)(row * SROW + seg * 4) * 4u;
            const float* src = W_hh + (size_t)row * HH + kc * 32 + seg * 4;
            CP_ASYNC16(bbase + soff, src, 16);
        }
        asm volatile("cp.async.commit_group;" ::: "memory");
    };

    issue_copy(0);

    for (int kc = 0; kc < 4; kc++) {
        if (kc + 1 < 4) {
            issue_copy(kc + 1);
            asm volatile("cp.async.wait_group 1;" ::: "memory");
        } else {
            asm volatile("cp.async.wait_group 0;" ::: "memory");
        }
        __syncthreads();

        const float* Af = smem + (kc & 1) * GH_STG;
        const float* Bf = Af + GH_ASZ;

        #pragma unroll
        for (int k8 = 0; k8 < 4; k8++) {
            const int k0 = k8 * 8;
            uint32_t afh[4], afl[4];
            {
                int r0 = wm*16 + gid;
                float a0 = Af[ r0      *SROW + k0 + tig    ];
                float a1 = Af[(r0 + 8) *SROW + k0 + tig    ];
                float a2 = Af[ r0      *SROW + k0 + tig + 4];
                float a3 = Af[(r0 + 8) *SROW + k0 + tig + 4];
                float h0 = tf32_rna(a0), h1 = tf32_rna(a1);
                float h2 = tf32_rna(a2), h3 = tf32_rna(a3);
                afh[0] = __float_as_uint(h0); afl[0] = __float_as_uint(a0 - h0);
                afh[1] = __float_as_uint(h1); afl[1] = __float_as_uint(a1 - h1);
                afh[2] = __float_as_uint(h2); afl[2] = __float_as_uint(a2 - h2);
                afh[3] = __float_as_uint(h3); afl[3] = __float_as_uint(a3 - h3);
            }
            #pragma unroll
            for (int g = 0; g < 3; g++) {
                #pragma unroll
                for (int nt = 0; nt < 4; nt++) {
                    int cb = g*128 + wn*32 + nt*8 + gid;
                    float b0 = Bf[cb*SROW + k0 + tig    ];
                    float b1 = Bf[cb*SROW + k0 + tig + 4];
                    uint32_t bfh[2], bfl[2];
                    float h0 = tf32_rna(b0), h1 = tf32_rna(b1);
                    bfh[0] = __float_as_uint(h0); bfl[0] = __float_as_uint(b0 - h0);
                    bfh[1] = __float_as_uint(h1); bfl[1] = __float_as_uint(b1 - h1);
                    MMA_TF32(acc[g][nt], afh, bfh);
                    MMA_TF32(acc[g][nt], afh, bfl);
                    MMA_TF32(acc[g][nt], afl, bfh);
                }
            }
        }
        __syncthreads();
    }

    // ---- register GRU epilogue: thread owns r/z/n for its (row,col) pairs ----
    #pragma unroll
    for (int nt = 0; nt < 4; nt++) {
        int col = wn*32 + nt*8 + 2*tig;
        float2 bhr = *(const float2*)(b_hh + col);
        float2 bhz = *(const float2*)(b_hh + 128 + col);
        float2 bhn = *(const float2*)(b_hh + 256 + col);
        #pragma unroll
        for (int half = 0; half < 2; half++) {
            int node = bm + wm*16 + gid + half*8;
            if (node >= NNODES) continue;
            size_t m = (size_t)node*8 + t;
            float2 gxr = *(const float2*)(g_GX + m*384 + col);
            float2 gxz = *(const float2*)(g_GX + m*384 + 128 + col);
            float2 gxn = *(const float2*)(g_GX + m*384 + 256 + col);
            float2 h   = *(const float2*)(g_H + (size_t)node*HH + col);
            float ghr0 = acc[0][nt][half*2+0] + bhr.x, ghr1 = acc[0][nt][half*2+1] + bhr.y;
            float ghz0 = acc[1][nt][half*2+0] + bhz.x, ghz1 = acc[1][nt][half*2+1] + bhz.y;
            float ghn0 = acc[2][nt][half*2+0] + bhn.x, ghn1 = acc[2][nt][half*2+1] + bhn.y;
            float r0 = sigmoidf_(gxr.x + ghr0), r1 = sigmoidf_(gxr.y + ghr1);
            float z0 = sigmoidf_(gxz.x + ghz0), z1 = sigmoidf_(gxz.y + ghz1);
            float n0 = tanhf(gxn.x + r0*ghn0),  n1 = tanhf(gxn.y + r1*ghn1);
            float2 hn;
            hn.x = (1.f - z0)*n0 + z0*h.x;
            hn.y = (1.f - z1)*n1 + z1*h.y;
            *(float2*)(g_H  + (size_t)node*HH + col) = hn;
            *(float2*)(g_HS + m*HH + col)            = hn;
        }
    }
}

// ======================= launch ==============================================
extern "C" void kernel_launch(void* const* d_in, const int* in_sizes, int n_in,
                              void* d_out, int out_size)
{
    const float* x     = (const float*)d_in[0];
    const void*  ei    = d_in[1];
    const float* Wl    = (const float*)d_in[2];
    const float* bl    = (const float*)d_in[3];
    const float* Wr    = (const float*)d_in[4];
    const float* W_ih  = (const float*)d_in[5];
    const float* b_ih  = (const float*)d_in[6];
    const float* W_hh  = (const float*)d_in[7];
    const float* b_hh  = (const float*)d_in[8];
    const float* W_rec = (const float*)d_in[9];
    const float* b_rec = (const float*)d_in[10];
    const float* W_c1  = (const float*)d_in[11];
    const float* b_c1  = (const float*)d_in[12];
    const float* W_c2  = (const float*)d_in[13];
    const float* b_c2  = (const float*)d_in[14];

    float* out      = (float*)d_out;
    float* outRecon = out;                          // [N,T,32] flat, row m
    float* outCls   = out + (size_t)MROWS * COUT;   // [N,T] flat, row m

    float *pAX, *pWcat, *pSP, *pGX, *pHS, *pWh, *pbh;
    cudaGetSymbolAddress((void**)&pAX,   g_AX);
    cudaGetSymbolAddress((void**)&pWcat, g_Wcat);
    cudaGetSymbolAddress((void**)&pSP,   g_SP);
    cudaGetSymbolAddress((void**)&pGX,   g_GX);
    cudaGetSymbolAddress((void**)&pHS,   g_HS);
    cudaGetSymbolAddress((void**)&pWh,   g_Wh);
    cudaGetSymbolAddress((void**)&pbh,   g_bh);

    cudaFuncSetAttribute(mma_gemm<2,1>, cudaFuncAttributeMaxDynamicSharedMemorySize, GSMEM);
    cudaFuncSetAttribute(mma_gemm<4,0>, cudaFuncAttributeMaxDynamicSharedMemorySize, GSMEM);
    cudaFuncSetAttribute(mma_gemm<4,2>, cudaFuncAttributeMaxDynamicSharedMemorySize, GSMEM);
    cudaFuncSetAttribute(ghgru_kernel,  cudaFuncAttributeMaxDynamicSharedMemorySize, GH_SMEM);

    // graph prep
    detect_kernel<<<1, 1>>>(ei);
    convert_kernel<<<(EDGES + 255)/256, 256>>>(ei);
    zero_kernel<<<1024, 256>>>();
    wcat_kernel<<<(HH*64 + 255)/256, 256>>>(Wl, Wr);
    headcat_kernel<<<(96*HH + 255)/256, 256>>>(W_rec, b_rec, W_c1, b_c1);
    count_kernel<<<(EDGES + 255)/256, 256>>>();
    scan_kernel<<<1, 1024>>>();
    fill_kernel<<<(EDGES + 255)/256, 256>>>();
    gather_kernel<<<NNODES, 256>>>(x);

    // SP = relu(AX @ Wcat^T + bl): [400000,64] -> [400000,128]
    mma_gemm<2,1><<<dim3(MROWS/128, 1), 512, GSMEM>>>(
        MROWS, 128, pAX, 64, pWcat, 64, bl, pSP, 128, nullptr, nullptr, nullptr);

    // GX = SP @ W_ih^T + b_ih: [400000,128] -> [400000,384]
    mma_gemm<4,0><<<dim3(MROWS/128, 3), 512, GSMEM>>>(
        MROWS, 384, pSP, 128, W_ih, 128, b_ih, pGX, 384, nullptr, nullptr, nullptr);

    // recurrence: fused GH GEMM + register GRU, 8 launches
    for (int t = 0; t < TT; t++)
        ghgru_kernel<<<(NNODES + 63)/64, 512, GH_SMEM>>>(t, W_hh, b_hh);

    // heads: recon (linear, ld32 -> d_out) + c1(relu, smem) + cls (fused)
    mma_gemm<4,2><<<dim3(MROWS/128, 1), 512, GSMEM>>>(
        MROWS, 96, pHS, 128, pWh, 128, pbh, outRecon, 32, W_c2, b_c2, outCls);
}

// round 10
// speedup vs baseline: 1.4518x; 1.0789x over previous
#include <cuda_runtime.h>
#include <math.h>
#include <stdint.h>

#define NNODES 50000
#define TT 8
#define HH 128
#define COUT 32
#define EDGES 800000
#define MROWS 400000

// ======================= scratch (device globals) ============================
__device__ int   g_is64;
__device__ int   g_src[EDGES];
__device__ int   g_dst[EDGES];
__device__ int   g_cnt[NNODES];
__device__ int   g_off[NNODES];
__device__ int   g_cur[NNODES];
__device__ int   g_adj[EDGES];
__device__ float g_AX [(size_t)MROWS*64];      // [m=(n*8+t), 64] = [agg/deg | x]
__device__ float g_Wcat[HH*64];                // [128, 64] = [Wl | Wr]
__device__ float g_Wh [96*HH];                 // [96, 128] = [W_rec ; W_c1]
__device__ float g_bh [96];
__device__ float g_GX [(size_t)MROWS*3*HH];    // [m, 384]
__device__ float g_H  [(size_t)NNODES*HH];     // [n, 128]
__device__ float g_HS [(size_t)MROWS*HH];      // [m, 128]

// ======================= helpers =============================================
__device__ __forceinline__ float tf32_rna(float v) {
    uint32_t r;
    asm("cvt.rna.tf32.f32 %0, %1;" : "=r"(r) : "f"(v));
    return __uint_as_float(r);
}
#define MMA_TF32(C, Af, Bf) \
    asm volatile( \
        "mma.sync.aligned.m16n8k8.row.col.f32.tf32.tf32.f32 " \
        "{%0,%1,%2,%3}, {%4,%5,%6,%7}, {%8,%9}, {%0,%1,%2,%3};" \
        : "+f"((C)[0]), "+f"((C)[1]), "+f"((C)[2]), "+f"((C)[3]) \
        : "r"((Af)[0]), "r"((Af)[1]), "r"((Af)[2]), "r"((Af)[3]), \
          "r"((Bf)[0]), "r"((Bf)[1]))
#define CP_ASYNC16(dst, src, sz) \
    asm volatile("cp.async.ca.shared.global [%0], [%1], 16, %2;" \
                 :: "r"(dst), "l"(src), "r"(sz))
__device__ __forceinline__ float sigmoidf_(float v) { return 1.f / (1.f + expf(-v)); }

// ======================= edge dtype detect + convert =========================
__global__ void detect_kernel(const void* ei) {
    const unsigned long long* p = (const unsigned long long*)ei;
    int is64 = 1;
    for (int i = 0; i < 1024; i++)
        if ((p[i] >> 32) != 0ull) { is64 = 0; break; }
    g_is64 = is64;
}
__global__ void convert_kernel(const void* ei) {
    int e = blockIdx.x * blockDim.x + threadIdx.x;
    if (e >= EDGES) return;
    int s, d;
    if (g_is64) {
        const long long* p = (const long long*)ei;
        s = (int)p[e]; d = (int)p[EDGES + e];
    } else {
        const int* p = (const int*)ei;
        s = p[e]; d = p[EDGES + e];
    }
    s = min(max(s, 0), NNODES - 1);
    d = min(max(d, 0), NNODES - 1);
    g_src[e] = s;
    g_dst[e] = d;
}

// ======================= graph prep ==========================================
__global__ void zero_kernel() {
    int idx = blockIdx.x * blockDim.x + threadIdx.x;
    int stride = gridDim.x * blockDim.x;
    for (int i = idx; i < NNODES; i += stride) g_cnt[i] = 0;
}
__global__ void count_kernel() {
    int e = blockIdx.x * blockDim.x + threadIdx.x;
    if (e < EDGES) atomicAdd(&g_cnt[g_dst[e]], 1);
}
__global__ void scan_kernel() {
    __shared__ int partial[1024];
    const int CH = (NNODES + 1023) / 1024;
    int t = threadIdx.x;
    int begin = t * CH;
    int end   = min(begin + CH, NNODES);
    int s = 0;
    for (int i = begin; i < end; i++) s += g_cnt[i];
    partial[t] = s;
    __syncthreads();
    #pragma unroll
    for (int d = 1; d < 1024; d <<= 1) {
        int v = (t >= d) ? partial[t - d] : 0;
        __syncthreads();
        partial[t] += v;
        __syncthreads();
    }
    int off = partial[t] - s;
    for (int i = begin; i < end; i++) {
        g_off[i] = off;
        g_cur[i] = off;
        off += g_cnt[i];
    }
}
__global__ void fill_kernel() {
    int e = blockIdx.x * blockDim.x + threadIdx.x;
    if (e >= EDGES) return;
    int pos = atomicAdd(&g_cur[g_dst[e]], 1);
    g_adj[pos] = g_src[e];
}
__global__ void __launch_bounds__(256) gather_kernel(const float* __restrict__ x) {
    int n   = blockIdx.x;
    int idx = threadIdx.x;
    int beg = g_off[n];
    int cnt = g_cnt[n];
    float s = 0.f;
    for (int p = beg; p < beg + cnt; p++) {
        int src = g_adj[p];
        s += x[(size_t)src * 256 + idx];
    }
    float dg = fmaxf((float)cnt, 1.f);
    int t = idx >> 5, c = idx & 31;
    size_t m = (size_t)n * 8 + t;
    g_AX[m * 64 + c]      = s / dg;
    g_AX[m * 64 + 32 + c] = x[(size_t)n * 256 + idx];
}
__global__ void wcat_kernel(const float* __restrict__ Wl, const float* __restrict__ Wr) {
    int idx = blockIdx.x * blockDim.x + threadIdx.x;
    if (idx >= HH*64) return;
    int j = idx >> 6, c = idx & 63;
    g_Wcat[idx] = (c < 32) ? Wl[j*32 + c] : Wr[j*32 + (c-32)];
}
__global__ void headcat_kernel(const float* __restrict__ W_rec, const float* __restrict__ b_rec,
                               const float* __restrict__ W_c1,  const float* __restrict__ b_c1) {
    int idx = blockIdx.x * blockDim.x + threadIdx.x;
    if (idx < 96*HH) {
        int r = idx >> 7, k = idx & 127;
        g_Wh[idx] = (r < 32) ? W_rec[r*128 + k] : W_c1[(r-32)*128 + k];
    }
    if (idx < 96) g_bh[idx] = (idx < 32) ? b_rec[idx] : b_c1[idx - 32];
}

// ======================= t=0 GRU (H0 = 0 => gh = b_hh) =======================
__global__ void gru0_kernel(const float* __restrict__ b_hh) {
    int idx = blockIdx.x * blockDim.x + threadIdx.x;
    if (idx >= NNODES*HH) return;
    int i = idx >> 7, j = idx & 127;
    size_t m = (size_t)i*8;
    float r  = sigmoidf_(g_GX[m*384 + j]       + b_hh[j]);
    float z  = sigmoidf_(g_GX[m*384 + 128 + j] + b_hh[128 + j]);
    float nn = tanhf(g_GX[m*384 + 256 + j] + r * b_hh[256 + j]);
    float hn = (1.f - z)*nn;
    g_H[idx]       = hn;
    g_HS[m*HH + j] = hn;
}

// ======================= common tiling constants =============================
#define SROW 36
#define SMAT (128*SROW)
#define GSMEM (2*2*SMAT*4)             /* 73728 B: 2 stages x (A+B) */
#define C1S   72                       /* head cls smem stride */

// ======================= fused SP+GX kernel ==================================
// Per 128-row block: phase 1 SP = relu(AX@Wcat^T + bl) -> smem (128x132);
// phase 2 GX[:, nt*128..] = SP@W_ih^T + b_ih for nt=0..2 (B 2-stage cp.async).
#define SPX_ST  132
#define SPX_OFF (4*SMAT)               /* SP tile offset in words */
#define SPX_SMEM ((4*SMAT + 128*SPX_ST)*4)   /* 141312 B */

__global__ void __launch_bounds__(512, 1) spgx_kernel(
    const float* __restrict__ W_ih,
    const float* __restrict__ bl,
    const float* __restrict__ b_ih)
{
    extern __shared__ float smem[];
    uint32_t smem_b;
    asm("{ .reg .u64 t; cvta.to.shared.u64 t, %1; cvt.u32.u64 %0, t; }"
        : "=r"(smem_b) : "l"(smem));

    const int tid  = threadIdx.x;
    const int lane = tid & 31;
    const int w    = tid >> 5;
    const int gid  = lane >> 2;
    const int tig  = lane & 3;
    const int wm   = w >> 2;
    const int wn   = w & 3;
    const int bm   = blockIdx.x * 128;
    float* SPs = smem + SPX_OFF;

    float acc[2][4][4];
    #pragma unroll
    for (int i = 0; i < 2; i++)
        #pragma unroll
        for (int j = 0; j < 4; j++)
            #pragma unroll
            for (int k = 0; k < 4; k++) acc[i][j][k] = 0.f;

    // ---------------- phase 1: SP = relu(AX @ Wcat^T + bl) ----------------
    auto issue_copy1 = [&](int kc) {
        const uint32_t abase = smem_b + (uint32_t)((kc & 1) * 2 * SMAT) * 4u;
        const uint32_t bbase = abase + (uint32_t)SMAT * 4u;
        #pragma unroll
        for (int h = 0; h < 2; h++) {
            int i   = tid + h * 512;
            int row = i >> 3;
            int seg = i & 7;
            uint32_t soff = (uint32_t)(row * SROW + seg * 4) * 4u;
            CP_ASYNC16(abase + soff, g_AX + (size_t)(bm + row) * 64 + kc * 32 + seg * 4, 16);
            CP_ASYNC16(bbase + soff, g_Wcat + (size_t)row * 64 + kc * 32 + seg * 4, 16);
        }
        asm volatile("cp.async.commit_group;" ::: "memory");
    };

    issue_copy1(0);
    for (int kc = 0; kc < 2; kc++) {
        if (kc == 0) {
            issue_copy1(1);
            asm volatile("cp.async.wait_group 1;" ::: "memory");
        } else {
            asm volatile("cp.async.wait_group 0;" ::: "memory");
        }
        __syncthreads();
        const float* Af = smem + (kc & 1) * 2 * SMAT;
        const float* Bf = Af + SMAT;
        #pragma unroll
        for (int k8 = 0; k8 < 4; k8++) {
            const int k0 = k8 * 8;
            float ar[2][4], br[4][2];
            #pragma unroll
            for (int mt = 0; mt < 2; mt++) {
                int r0 = wm*32 + mt*16 + gid;
                ar[mt][0] = Af[ r0      *SROW + k0 + tig    ];
                ar[mt][1] = Af[(r0 + 8) *SROW + k0 + tig    ];
                ar[mt][2] = Af[ r0      *SROW + k0 + tig + 4];
                ar[mt][3] = Af[(r0 + 8) *SROW + k0 + tig + 4];
            }
            #pragma unroll
            for (int nt = 0; nt < 4; nt++) {
                int cb = wn*32 + nt*8 + gid;
                br[nt][0] = Bf[cb*SROW + k0 + tig    ];
                br[nt][1] = Bf[cb*SROW + k0 + tig + 4];
            }
            uint32_t afh[2][4], afl[2][4], bfh[4][2], bfl[4][2];
            #pragma unroll
            for (int mt = 0; mt < 2; mt++)
                #pragma unroll
                for (int q = 0; q < 4; q++) {
                    float hi = tf32_rna(ar[mt][q]);
                    afh[mt][q] = __float_as_uint(hi);
                    afl[mt][q] = __float_as_uint(ar[mt][q] - hi);
                }
            #pragma unroll
            for (int nt = 0; nt < 4; nt++)
                #pragma unroll
                for (int q = 0; q < 2; q++) {
                    float hi = tf32_rna(br[nt][q]);
                    bfh[nt][q] = __float_as_uint(hi);
                    bfl[nt][q] = __float_as_uint(br[nt][q] - hi);
                }
            #pragma unroll
            for (int mt = 0; mt < 2; mt++)
                #pragma unroll
                for (int nt = 0; nt < 4; nt++) {
                    MMA_TF32(acc[mt][nt], afh[mt], bfh[nt]);
                    MMA_TF32(acc[mt][nt], afh[mt], bfl[nt]);
                    MMA_TF32(acc[mt][nt], afl[mt], bfh[nt]);
                }
        }
        __syncthreads();
    }
    // stage relu(SP) into smem
    #pragma unroll
    for (int mt = 0; mt < 2; mt++)
        #pragma unroll
        for (int nt = 0; nt < 4; nt++) {
            int col = wn*32 + nt*8 + 2*tig;
            #pragma unroll
            for (int half = 0; half < 2; half++) {
                int lrow = wm*32 + mt*16 + gid + half*8;
                float vx = fmaxf(acc[mt][nt][half*2 + 0] + bl[col],     0.f);
                float vy = fmaxf(acc[mt][nt][half*2 + 1] + bl[col + 1], 0.f);
                SPs[lrow*SPX_ST + col]     = vx;
                SPs[lrow*SPX_ST + col + 1] = vy;
            }
        }
    __syncthreads();

    // ---------------- phase 2: GX = SP @ W_ih^T + b_ih (3 N-subtiles) -------
    auto issue_copyB = [&](int idx) {   // idx = nt*4 + kc
        int nt = idx >> 2, kc = idx & 3;
        const uint32_t bbase = smem_b + (uint32_t)((idx & 1) * 2 * SMAT) * 4u;
        #pragma unroll
        for (int h = 0; h < 2; h++) {
            int i   = tid + h * 512;
            int row = i >> 3;
            int seg = i & 7;
            uint32_t soff = (uint32_t)(row * SROW + seg * 4) * 4u;
            CP_ASYNC16(bbase + soff, W_ih + (size_t)(nt*128 + row)*128 + kc*32 + seg*4, 16);
        }
        asm volatile("cp.async.commit_group;" ::: "memory");
    };

    issue_copyB(0);
    for (int nt3 = 0; nt3 < 3; nt3++) {
        #pragma unroll
        for (int i = 0; i < 2; i++)
            #pragma unroll
            for (int j = 0; j < 4; j++)
                #pragma unroll
                for (int k = 0; k < 4; k++) acc[i][j][k] = 0.f;

        for (int kc = 0; kc < 4; kc++) {
            int idx = nt3*4 + kc;
            if (idx + 1 < 12) {
                issue_copyB(idx + 1);
                asm volatile("cp.async.wait_group 1;" ::: "memory");
            } else {
                asm volatile("cp.async.wait_group 0;" ::: "memory");
            }
            __syncthreads();
            const float* Bf = smem + (idx & 1) * 2 * SMAT;

            #pragma unroll
            for (int k8 = 0; k8 < 4; k8++) {
                const int k0 = kc*32 + k8*8;      // SP column (K index)
                const int kb = k8*8;              // B smem k index
                float ar[2][4], br[4][2];
                #pragma unroll
                for (int mt = 0; mt < 2; mt++) {
                    int r0 = wm*32 + mt*16 + gid;
                    ar[mt][0] = SPs[ r0      *SPX_ST + k0 + tig    ];
                    ar[mt][1] = SPs[(r0 + 8) *SPX_ST + k0 + tig    ];
                    ar[mt][2] = SPs[ r0      *SPX_ST + k0 + tig + 4];
                    ar[mt][3] = SPs[(r0 + 8) *SPX_ST + k0 + tig + 4];
                }
                #pragma unroll
                for (int nt = 0; nt < 4; nt++) {
                    int cb = wn*32 + nt*8 + gid;
                    br[nt][0] = Bf[cb*SROW + kb + tig    ];
                    br[nt][1] = Bf[cb*SROW + kb + tig + 4];
                }
                uint32_t afh[2][4], afl[2][4], bfh[4][2], bfl[4][2];
                #pragma unroll
                for (int mt = 0; mt < 2; mt++)
                    #pragma unroll
                    for (int q = 0; q < 4; q++) {
                        float hi = tf32_rna(ar[mt][q]);
                        afh[mt][q] = __float_as_uint(hi);
                        afl[mt][q] = __float_as_uint(ar[mt][q] - hi);
                    }
                #pragma unroll
                for (int nt = 0; nt < 4; nt++)
                    #pragma unroll
                    for (int q = 0; q < 2; q++) {
                        float hi = tf32_rna(br[nt][q]);
                        bfh[nt][q] = __float_as_uint(hi);
                        bfl[nt][q] = __float_as_uint(br[nt][q] - hi);
                    }
                #pragma unroll
                for (int mt = 0; mt < 2; mt++)
                    #pragma unroll
                    for (int nt = 0; nt < 4; nt++) {
                        MMA_TF32(acc[mt][nt], afh[mt], bfh[nt]);
                        MMA_TF32(acc[mt][nt], afh[mt], bfl[nt]);
                        MMA_TF32(acc[mt][nt], afl[mt], bfh[nt]);
                    }
            }
            __syncthreads();
        }

        // write GX subtile
        #pragma unroll
        for (int mt = 0; mt < 2; mt++)
            #pragma unroll
            for (int nt = 0; nt < 4; nt++) {
                int col = nt3*128 + wn*32 + nt*8 + 2*tig;
                #pragma unroll
                for (int half = 0; half < 2; half++) {
                    int row = bm + wm*32 + mt*16 + gid + half*8;
                    float2 o;
                    o.x = acc[mt][nt][half*2 + 0] + b_ih[col];
                    o.y = acc[mt][nt][half*2 + 1] + b_ih[col + 1];
                    *(float2*)(g_GX + (size_t)row*384 + col) = o;
                }
            }
    }
}

// ======================= head GEMM + fused cls ===============================
__global__ void __launch_bounds__(512, 1) head_kernel(
    const float* __restrict__ w2, const float* __restrict__ b2,
    float* __restrict__ recon, float* __restrict__ clsOut)
{
    extern __shared__ float smem[];
    uint32_t smem_b;
    asm("{ .reg .u64 t; cvta.to.shared.u64 t, %1; cvt.u32.u64 %0, t; }"
        : "=r"(smem_b) : "l"(smem));

    const int tid  = threadIdx.x;
    const int lane = tid & 31;
    const int w    = tid >> 5;
    const int gid  = lane >> 2;
    const int tig  = lane & 3;
    const int wm   = w >> 2;
    const int wn   = w & 3;
    const int bm   = blockIdx.x * 128;

    float acc[2][4][4];
    #pragma unroll
    for (int i = 0; i < 2; i++)
        #pragma unroll
        for (int j = 0; j < 4; j++)
            #pragma unroll
            for (int k = 0; k < 4; k++) acc[i][j][k] = 0.f;

    auto issue_copy = [&](int kc) {
        const uint32_t abase = smem_b + (uint32_t)((kc & 1) * 2 * SMAT) * 4u;
        const uint32_t bbase = abase + (uint32_t)SMAT * 4u;
        #pragma unroll
        for (int h = 0; h < 2; h++) {
            int i   = tid + h * 512;
            int row = i >> 3;
            int seg = i & 7;
            uint32_t soff = (uint32_t)(row * SROW + seg * 4) * 4u;
            CP_ASYNC16(abase + soff, g_HS + (size_t)(bm + row)*128 + kc*32 + seg*4, 16);
            CP_ASYNC16(bbase + soff, g_Wh + (size_t)min(row, 95)*128 + kc*32 + seg*4,
                       (row < 96) ? 16 : 0);
        }
        asm volatile("cp.async.commit_group;" ::: "memory");
    };

    issue_copy(0);
    for (int kc = 0; kc < 4; kc++) {
        if (kc + 1 < 4) {
            issue_copy(kc + 1);
            asm volatile("cp.async.wait_group 1;" ::: "memory");
        } else {
            asm volatile("cp.async.wait_group 0;" ::: "memory");
        }
        __syncthreads();
        const float* Af = smem + (kc & 1) * 2 * SMAT;
        const float* Bf = Af + SMAT;
        #pragma unroll
        for (int k8 = 0; k8 < 4; k8++) {
            const int k0 = k8 * 8;
            float ar[2][4], br[4][2];
            #pragma unroll
            for (int mt = 0; mt < 2; mt++) {
                int r0 = wm*32 + mt*16 + gid;
                ar[mt][0] = Af[ r0      *SROW + k0 + tig    ];
                ar[mt][1] = Af[(r0 + 8) *SROW + k0 + tig    ];
                ar[mt][2] = Af[ r0      *SROW + k0 + tig + 4];
                ar[mt][3] = Af[(r0 + 8) *SROW + k0 + tig + 4];
            }
            #pragma unroll
            for (int nt = 0; nt < 4; nt++) {
                int cb = wn*32 + nt*8 + gid;
                br[nt][0] = Bf[cb*SROW + k0 + tig    ];
                br[nt][1] = Bf[cb*SROW + k0 + tig + 4];
            }
            uint32_t afh[2][4], afl[2][4], bfh[4][2], bfl[4][2];
            #pragma unroll
            for (int mt = 0; mt < 2; mt++)
                #pragma unroll
                for (int q = 0; q < 4; q++) {
                    float hi = tf32_rna(ar[mt][q]);
                    afh[mt][q] = __float_as_uint(hi);
                    afl[mt][q] = __float_as_uint(ar[mt][q] - hi);
                }
            #pragma unroll
            for (int nt = 0; nt < 4; nt++)
                #pragma unroll
                for (int q = 0; q < 2; q++) {
                    float hi = tf32_rna(br[nt][q]);
                    bfh[nt][q] = __float_as_uint(hi);
                    bfl[nt][q] = __float_as_uint(br[nt][q] - hi);
                }
            #pragma unroll
            for (int mt = 0; mt < 2; mt++)
                #pragma unroll
                for (int nt = 0; nt < 4; nt++) {
                    MMA_TF32(acc[mt][nt], afh[mt], bfh[nt]);
                    MMA_TF32(acc[mt][nt], afh[mt], bfl[nt]);
                    MMA_TF32(acc[mt][nt], afl[mt], bfh[nt]);
                }
        }
        __syncthreads();
    }

    #pragma unroll
    for (int mt = 0; mt < 2; mt++)
        #pragma unroll
        for (int nt = 0; nt < 4; nt++) {
            int col = wn*32 + nt*8 + 2*tig;
            if (col >= 96) continue;
            #pragma unroll
            for (int half = 0; half < 2; half++) {
                int row = bm + wm*32 + mt*16 + gid + half*8;
                float2 o;
                o.x = acc[mt][nt][half*2 + 0] + g_bh[col];
                o.y = acc[mt][nt][half*2 + 1] + g_bh[col + 1];
                if (col < 32) {
                    *(float2*)(recon + (size_t)row*32 + col) = o;
                } else {
                    int lrow = row - bm;
                    smem[lrow*C1S + col - 32]     = fmaxf(o.x, 0.f);
                    smem[lrow*C1S + col - 32 + 1] = fmaxf(o.y, 0.f);
                }
            }
        }
    __syncthreads();
    #pragma unroll
    for (int rr = 0; rr < 8; rr++) {
        int lrow = w*8 + rr;
        float s = smem[lrow*C1S + lane]      * w2[lane]
                + smem[lrow*C1S + 32 + lane] * w2[32 + lane];
        #pragma unroll
        for (int o = 16; o; o >>= 1) s += __shfl_xor_sync(0xffffffffu, s, o);
        if (lane == 0) clsOut[bm + lrow] = sigmoidf_(s + b2[0]);
    }
}

// ======================= fused GH GEMM + register GRU (t>=1) =================
#define GH_ASZ  (64*SROW)
#define GH_BSZ  (384*SROW)
#define GH_STG  (GH_ASZ + GH_BSZ)
#define GH_SMEM (2*GH_STG*4)

__global__ void __launch_bounds__(512, 1) ghgru_kernel(
    int t,
    const float* __restrict__ W_hh,
    const float* __restrict__ b_hh)
{
    extern __shared__ float smem[];
    uint32_t smem_b;
    asm("{ .reg .u64 t; cvta.to.shared.u64 t, %1; cvt.u32.u64 %0, t; }"
        : "=r"(smem_b) : "l"(smem));

    const int tid  = threadIdx.x;
    const int lane = tid & 31;
    const int w    = tid >> 5;
    const int gid  = lane >> 2;
    const int tig  = lane & 3;
    const int wm   = w >> 2;
    const int wn   = w & 3;
    const int bm   = blockIdx.x * 64;

    float acc[3][4][4];
    #pragma unroll
    for (int g = 0; g < 3; g++)
        #pragma unroll
        for (int j = 0; j < 4; j++)
            #pragma unroll
            for (int k = 0; k < 4; k++) acc[g][j][k] = 0.f;

    auto issue_copy = [&](int kc) {
        const int s = kc & 1;
        const uint32_t abase = smem_b + (uint32_t)(s * GH_STG) * 4u;
        const uint32_t bbase = abase + (uint32_t)GH_ASZ * 4u;
        {
            int row = tid >> 3;
            int seg = tid & 7;
            uint32_t soff = (uint32_t)(row * SROW + seg * 4) * 4u;
            int grow = bm + row;
            CP_ASYNC16(abase + soff,
                       g_H + (size_t)min(grow, NNODES - 1) * HH + kc * 32 + seg * 4,
                       (grow < NNODES) ? 16 : 0);
        }
        #pragma unroll
        for (int h = 0; h < 6; h++) {
            int i   = tid + h * 512;
            int row = i >> 3;
            int seg = i & 7;
            uint32_t soff = (uint32_t)(row * SROW + seg * 4) * 4u;
            CP_ASYNC16(bbase + soff, W_hh + (size_t)row * HH + kc * 32 + seg * 4, 16);
        }
        asm volatile("cp.async.commit_group;" ::: "memory");
    };

    issue_copy(0);
    for (int kc = 0; kc < 4; kc++) {
        if (kc + 1 < 4) {
            issue_copy(kc + 1);
            asm volatile("cp.async.wait_group 1;" ::: "memory");
        } else {
            asm volatile("cp.async.wait_group 0;" ::: "memory");
        }
        __syncthreads();
        const float* Af = smem + (kc & 1) * GH_STG;
        const float* Bf = Af + GH_ASZ;
        #pragma unroll
        for (int k8 = 0; k8 < 4; k8++) {
            const int k0 = k8 * 8;
            uint32_t afh[4], afl[4];
            {
                int r0 = wm*16 + gid;
                float a0 = Af[ r0      *SROW + k0 + tig    ];
                float a1 = Af[(r0 + 8) *SROW + k0 + tig    ];
                float a2 = Af[ r0      *SROW + k0 + tig + 4];
                float a3 = Af[(r0 + 8) *SROW + k0 + tig + 4];
                float h0 = tf32_rna(a0), h1 = tf32_rna(a1);
                float h2 = tf32_rna(a2), h3 = tf32_rna(a3);
                afh[0] = __float_as_uint(h0); afl[0] = __float_as_uint(a0 - h0);
                afh[1] = __float_as_uint(h1); afl[1] = __float_as_uint(a1 - h1);
                afh[2] = __float_as_uint(h2); afl[2] = __float_as_uint(a2 - h2);
                afh[3] = __float_as_uint(h3); afl[3] = __float_as_uint(a3 - h3);
            }
            #pragma unroll
            for (int g = 0; g < 3; g++) {
                #pragma unroll
                for (int nt = 0; nt < 4; nt++) {
                    int cb = g*128 + wn*32 + nt*8 + gid;
                    float b0 = Bf[cb*SROW + k0 + tig    ];
                    float b1 = Bf[cb*SROW + k0 + tig + 4];
                    uint32_t bfh[2], bfl[2];
                    float h0 = tf32_rna(b0), h1 = tf32_rna(b1);
                    bfh[0] = __float_as_uint(h0); bfl[0] = __float_as_uint(b0 - h0);
                    bfh[1] = __float_as_uint(h1); bfl[1] = __float_as_uint(b1 - h1);
                    MMA_TF32(acc[g][nt], afh, bfh);
                    MMA_TF32(acc[g][nt], afh, bfl);
                    MMA_TF32(acc[g][nt], afl, bfh);
                }
            }
        }
        __syncthreads();
    }

    #pragma unroll
    for (int nt = 0; nt < 4; nt++) {
        int col = wn*32 + nt*8 + 2*tig;
        float2 bhr = *(const float2*)(b_hh + col);
        float2 bhz = *(const float2*)(b_hh + 128 + col);
        float2 bhn = *(const float2*)(b_hh + 256 + col);
        #pragma unroll
        for (int half = 0; half < 2; half++) {
            int node = bm + wm*16 + gid + half*8;
            if (node >= NNODES) continue;
            size_t m = (size_t)node*8 + t;
            float2 gxr = *(const float2*)(g_GX + m*384 + col);
            float2 gxz = *(const float2*)(g_GX + m*384 + 128 + col);
            float2 gxn = *(const float2*)(g_GX + m*384 + 256 + col);
            float2 h   = *(const float2*)(g_H + (size_t)node*HH + col);
            float ghr0 = acc[0][nt][half*2+0] + bhr.x, ghr1 = acc[0][nt][half*2+1] + bhr.y;
            float ghz0 = acc[1][nt][half*2+0] + bhz.x, ghz1 = acc[1][nt][half*2+1] + bhz.y;
            float ghn0 = acc[2][nt][half*2+0] + bhn.x, ghn1 = acc[2][nt][half*2+1] + bhn.y;
            float r0 = sigmoidf_(gxr.x + ghr0), r1 = sigmoidf_(gxr.y + ghr1);
            float z0 = sigmoidf_(gxz.x + ghz0), z1 = sigmoidf_(gxz.y + ghz1);
            float n0 = tanhf(gxn.x + r0*ghn0),  n1 = tanhf(gxn.y + r1*ghn1);
            float2 hn;
            hn.x = (1.f - z0)*n0 + z0*h.x;
            hn.y = (1.f - z1)*n1 + z1*h.y;
            *(float2*)(g_H  + (size_t)node*HH + col) = hn;
            *(float2*)(g_HS + m*HH + col)            = hn;
        }
    }
}

// ======================= launch ==============================================
extern "C" void kernel_launch(void* const* d_in, const int* in_sizes, int n_in,
                              void* d_out, int out_size)
{
    const float* x     = (const float*)d_in[0];
    const void*  ei    = d_in[1];
    const float* Wl    = (const float*)d_in[2];
    const float* bl    = (const float*)d_in[3];
    const float* Wr    = (const float*)d_in[4];
    const float* W_ih  = (const float*)d_in[5];
    const float* b_ih  = (const float*)d_in[6];
    const float* W_hh  = (const float*)d_in[7];
    const float* b_hh  = (const float*)d_in[8];
    const float* W_rec = (const float*)d_in[9];
    const float* b_rec = (const float*)d_in[10];
    const float* W_c1  = (const float*)d_in[11];
    const float* b_c1  = (const float*)d_in[12];
    const float* W_c2  = (const float*)d_in[13];
    const float* b_c2  = (const float*)d_in[14];

    float* out      = (float*)d_out;
    float* outRecon = out;
    float* outCls   = out + (size_t)MROWS * COUT;

    cudaFuncSetAttribute(spgx_kernel,  cudaFuncAttributeMaxDynamicSharedMemorySize, SPX_SMEM);
    cudaFuncSetAttribute(head_kernel,  cudaFuncAttributeMaxDynamicSharedMemorySize, GSMEM);
    cudaFuncSetAttribute(ghgru_kernel, cudaFuncAttributeMaxDynamicSharedMemorySize, GH_SMEM);

    // graph prep
    detect_kernel<<<1, 1>>>(ei);
    convert_kernel<<<(EDGES + 255)/256, 256>>>(ei);
    zero_kernel<<<256, 256>>>();
    wcat_kernel<<<(HH*64 + 255)/256, 256>>>(Wl, Wr);
    headcat_kernel<<<(96*HH + 255)/256, 256>>>(W_rec, b_rec, W_c1, b_c1);
    count_kernel<<<(EDGES + 255)/256, 256>>>();
    scan_kernel<<<1, 1024>>>();
    fill_kernel<<<(EDGES + 255)/256, 256>>>();
    gather_kernel<<<NNODES, 256>>>(x);

    // fused SP+GX: [400000,64] -> relu -> [400000,384]
    spgx_kernel<<<MROWS/128, 512, SPX_SMEM>>>(W_ih, bl, b_ih);

    // recurrence: t=0 pointwise (H0=0), t>=1 fused GEMM+GRU
    gru0_kernel<<<(NNODES*HH + 255)/256, 256>>>(b_hh);
    for (int t = 1; t < TT; t++)
        ghgru_kernel<<<(NNODES + 63)/64, 512, GH_SMEM>>>(t, W_hh, b_hh);

    // heads: recon -> d_out, c1 -> smem -> cls -> d_out
    head_kernel<<<MROWS/128, 512, GSMEM>>>(W_c2, b_c2, outRecon, outCls);
}